// round 16
// baseline (speedup 1.0000x reference)
#include <cuda_runtime.h>
#include <cuda_bf16.h>
#include <cuda_fp16.h>
#include <math.h>
#include <stdint.h>

// Problem dims (fixed by the dataset)
#define BB 8
#define SS 512
#define EE 2048
#define HH 2048
#define MM (BB*SS)   // 4096 rows
#define CH 16        // scan chunks
#define CT 32        // steps per chunk

// ---------------- scratch (__device__ globals; no allocation allowed) ----------------
__device__ __nv_bfloat16 g_Aq [(size_t)MM * EE];        // integer q as bf16 (exact)
__device__ float         g_invs[MM];                    // 1/s per row
__device__ __nv_bfloat16 g_Acg[(size_t)MM * 2 * EE];    // [hi | lo] split of x
__device__ __nv_bfloat16 g_Bf  [(size_t)HH * EE];       // W_f^T  [N,K]
__device__ __nv_bfloat16 g_Bc  [(size_t)HH * EE];       // W_c^T
__device__ __nv_bfloat16 g_Bg  [(size_t)HH * EE];       // W_g^T
__device__ __nv_bfloat16 g_Bcgn[(size_t)HH * EE];       // W_g native [N,K] (CG gate)
__device__ __align__(16) __half g_F [(size_t)MM * HH];  // gate in (0,1) -> fp16
__device__ __align__(16) __half g_C [(size_t)MM * HH];  // silu values -> fp16
__device__ __align__(16) __half g_G [(size_t)MM * HH];  // gate -> fp16
__device__ __align__(16) __half g_CG[(size_t)MM * HH];  // gate -> fp16
__device__ float g_chA[BB * CH * HH];
__device__ float g_chS[BB * CH * HH];
__device__ float g_hin[BB * CH * HH];

// ---------------- helpers ----------------
__device__ __forceinline__ uint32_t smem_u32(const void* p) {
    uint32_t a;
    asm("{ .reg .u64 t; cvta.to.shared.u64 t, %1; cvt.u32.u64 %0, t; }" : "=r"(a) : "l"(p));
    return a;
}
#define CP_ASYNC16(smem, gmem) \
    asm volatile("cp.async.cg.shared.global [%0], [%1], 16;" :: "r"((uint32_t)(smem)), "l"(gmem) : "memory")
#define CP_COMMIT() asm volatile("cp.async.commit_group;" ::: "memory")
#define CP_WAIT(n)  asm volatile("cp.async.wait_group %0;" :: "n"(n) : "memory")

#define LDSM4(r0, r1, r2, r3, addr) \
    asm volatile("ldmatrix.sync.aligned.m8n8.x4.shared.b16 {%0,%1,%2,%3}, [%4];" \
        : "=r"(r0), "=r"(r1), "=r"(r2), "=r"(r3) : "r"(addr))

#define MMA16816(d, a, b0, b1) \
    asm volatile("mma.sync.aligned.m16n8k16.row.col.f32.bf16.bf16.f32 " \
        "{%0,%1,%2,%3}, {%4,%5,%6,%7}, {%8,%9}, {%0,%1,%2,%3};" \
        : "+f"((d)[0]), "+f"((d)[1]), "+f"((d)[2]), "+f"((d)[3]) \
        : "r"((a)[0]), "r"((a)[1]), "r"((a)[2]), "r"((a)[3]), "r"(b0), "r"(b1))

#define SWZ(o) ((o) ^ ((((uint32_t)(o)) >> 3) & 0x70))

// FMA-only sigmoid (no MUFU): exp2 poly + Newton reciprocal, rel err ~1e-6
__device__ __forceinline__ float fast_sigmoid(float v) {
    float t = v * 1.4426950408889634f;
    t = fminf(fmaxf(t, -126.0f), 126.0f);
    float fi = rintf(t);
    float f = t - fi;
    float p = 1.3333558146428443e-3f;
    p = fmaf(p, f, 9.6181291976126507e-3f);
    p = fmaf(p, f, 5.5504108664821580e-2f);
    p = fmaf(p, f, 2.4022650695910071e-1f);
    p = fmaf(p, f, 6.9314718055994531e-1f);
    p = fmaf(p, f, 1.0f);
    float e = p * __int_as_float(((int)fi + 127) << 23);
    float a = 1.0f + e;
    float r = __int_as_float(0x7EF311C3 - __float_as_int(a));
    r = r * fmaf(-a, r, 2.0f);
    r = r * fmaf(-a, r, 2.0f);
    r = r * fmaf(-a, r, 2.0f);
    return e * r;
}

__device__ __forceinline__ void store8bf16(__nv_bfloat16* p, const float* f) {
    __nv_bfloat162 p0 = __floats2bfloat162_rn(f[0], f[1]);
    __nv_bfloat162 p1 = __floats2bfloat162_rn(f[2], f[3]);
    __nv_bfloat162 p2 = __floats2bfloat162_rn(f[4], f[5]);
    __nv_bfloat162 p3 = __floats2bfloat162_rn(f[6], f[7]);
    uint4 u;
    u.x = *(uint32_t*)&p0; u.y = *(uint32_t*)&p1;
    u.z = *(uint32_t*)&p2; u.w = *(uint32_t*)&p3;
    *(uint4*)p = u;
}

// ===== 1) fused prep: quantsplit rows (bid < MM) + weight prep (bid >= MM) =====
__global__ __launch_bounds__(256) void prep_kernel(
    const float* __restrict__ x, const float* __restrict__ rms_scale,
    const float* __restrict__ Wf, const float* __restrict__ Wc, const float* __restrict__ Wg)
{
    __shared__ float red_a[8], red_b[8];
    __shared__ float bcast[2];
    __shared__ float tile[32][33];
    const int tid = threadIdx.x;

    if (blockIdx.x >= MM) {
        // ---- weight prep: 4 sets of 4096 blocks (64x64 grid each) ----
        int w = blockIdx.x - MM;          // 0..16383
        int zi = w >> 12;                 // 0..3
        int rem = w & 4095;
        int bx = rem & 63, by = rem >> 6;
        int tx = tid & 31, ty = tid >> 5; // 32x8
        if (zi == 3) {
            // native-layout W_g -> bf16 (CG gate B)
            int xI = bx * 32 + tx;
            int yI = by * 32 + ty;
#pragma unroll
            for (int j = 0; j < 32; j += 8) {
                size_t idx = (size_t)(yI + j) * EE + xI;
                g_Bcgn[idx] = __float2bfloat16(Wg[idx]);
            }
            return;
        }
        const float* in = (zi == 0) ? Wf : (zi == 1) ? Wc : Wg;
        __nv_bfloat16* out = (zi == 0) ? g_Bf : (zi == 1) ? g_Bc : g_Bg;
        int xI = bx * 32 + tx;            // H index (contig in input)
        int yI = by * 32 + ty;            // E index
#pragma unroll
        for (int j = 0; j < 32; j += 8)
            tile[ty + j][tx] = in[(size_t)(yI + j) * HH + xI];
        __syncthreads();
        xI = by * 32 + tx;                // E index (contig in output)
        yI = bx * 32 + ty;                // H index
#pragma unroll
        for (int j = 0; j < 32; j += 8)
            out[(size_t)(yI + j) * EE + xI] = __float2bfloat16(tile[tx][ty + j]);
        return;
    }

    // ---- quantsplit: rms_norm + act_quant + hi/lo split ----
    const int row = blockIdx.x;
    const float* xr = x + (size_t)row * EE;

    float v[8];
    float ss = 0.f;
#pragma unroll
    for (int i = 0; i < 8; i += 4) {
        float4 t4 = *(const float4*)(xr + tid * 8 + i);
        v[i] = t4.x; v[i+1] = t4.y; v[i+2] = t4.z; v[i+3] = t4.w;
    }
#pragma unroll
    for (int i = 0; i < 8; i++) ss += v[i] * v[i];
#pragma unroll
    for (int o = 16; o; o >>= 1) ss += __shfl_xor_sync(0xffffffffu, ss, o);
    if ((tid & 31) == 0) red_a[tid >> 5] = ss;
    __syncthreads();
    if (tid == 0) {
        float t = 0.f;
#pragma unroll
        for (int w = 0; w < 8; w++) t += red_a[w];
        bcast[0] = 1.0f / sqrtf(t / (float)EE + 1e-5f);
    }
    __syncthreads();
    const float rms = bcast[0];

    {
        float hi[8], lo[8];
#pragma unroll
        for (int i = 0; i < 8; i++) {
            __nv_bfloat16 h = __float2bfloat16(v[i]);
            hi[i] = __bfloat162float(h);
            lo[i] = v[i] - hi[i];
        }
        size_t off = (size_t)row * (2 * EE) + tid * 8;
        store8bf16(g_Acg + off, hi);
        store8bf16(g_Acg + off + EE, lo);
    }

    float sv[8];
    float msc = 0.f;
#pragma unroll
    for (int i = 0; i < 8; i++) {
        sv[i] = v[i] * rms * rms_scale[tid * 8 + i];
        msc = fmaxf(msc, fabsf(sv[i]));
    }
#pragma unroll
    for (int o = 16; o; o >>= 1) msc = fmaxf(msc, __shfl_xor_sync(0xffffffffu, msc, o));
    if ((tid & 31) == 0) red_b[tid >> 5] = msc;
    __syncthreads();
    if (tid == 0) {
        float m = 0.f;
#pragma unroll
        for (int w = 0; w < 8; w++) m = fmaxf(m, red_b[w]);
        float s = 127.0f / (m + 1e-5f);
        s = fminf(fmaxf(s, 0.001f), 1000.0f);
        bcast[1] = s;
        g_invs[row] = 1.0f / s;
    }
    __syncthreads();
    const float s = bcast[1];
    {
        float q[8];
#pragma unroll
        for (int i = 0; i < 8; i++) {
            float qq = rintf(s * sv[i]);                 // ties-to-even == jnp.round
            q[i] = fminf(fmaxf(qq, -128.0f), 127.0f);
        }
        store8bf16(g_Aq + (size_t)row * EE + tid * 8, q);
    }
}

// ===== GEMM tile body (round-7 mainloop, frozen) =====
#define STAGES 3
#define STAGE_BYTES 32768                       // 16KB A + 16KB B (128 rows x 128B)
#define GEMM_SMEM (STAGES * STAGE_BYTES)        // 96 KB -> 2 CTAs/SM

__device__ __forceinline__ void gemm_tile(
    int gid, int m0, int n0, char* smem,
    const float* __restrict__ bfp, const float* __restrict__ bcp, const float* __restrict__ bgp)
{
    const uint32_t sb = smem_u32(smem);
    const int tid = threadIdx.x, wid = tid >> 5, lid = tid & 31;
    const int K = (gid == 3) ? 2 * EE : EE;
    const int NC = K / 64;
    const size_t Kz = (size_t)K;

    const __nv_bfloat16* A = (gid == 3) ? g_Acg : g_Aq;
    const __nv_bfloat16* B = (gid == 0) ? g_Bf : (gid == 1) ? g_Bc : (gid == 2) ? g_Bg : g_Bcgn;

    const int wm = (wid >> 2) * 64;   // warp m offset (0/64)
    const int wn = (wid & 3) * 32;    // warp n offset (0/32/64/96)

    uint32_t pA[4], xA[4];
#pragma unroll
    for (int mt = 0; mt < 4; mt++) {
        int row = wm + mt * 16 + (lid & 15);
        pA[mt] = (uint32_t)row * 128;
        xA[mt] = (uint32_t)(row & 7) * 16;
    }
    const uint32_t hiA = (lid >> 4) * 16;
    uint32_t pB[2], xB[2];
#pragma unroll
    for (int nt2 = 0; nt2 < 2; nt2++) {
        int row = wn + nt2 * 16 + (lid & 7) + ((lid >> 4) & 1) * 8;
        pB[nt2] = (uint32_t)row * 128 + 16384;
        xB[nt2] = (uint32_t)(row & 7) * 16;
    }
    const uint32_t hiB = ((lid >> 3) & 1) * 16;

    const int row0 = tid >> 3, c16 = tid & 7;
    const char* gA = (const char*)A + ((size_t)(m0 + row0) * Kz) * 2 + c16 * 16;
    const char* gB = (const char*)B + ((size_t)(n0 + row0) * EE) * 2 + c16 * 16;
    const size_t jstrA = (size_t)32 * Kz * 2;
    const size_t jstrB = (size_t)32 * EE * 2;
    uint32_t so[4];
#pragma unroll
    for (int j = 0; j < 4; j++) so[j] = SWZ((uint32_t)(row0 + 32 * j) * 128 + c16 * 16);

#define LOAD_STAGE(c, s) do { \
        uint32_t _sa = sb + (s) * STAGE_BYTES; \
        const char* _ga = gA + (size_t)(c) * 128; \
        const char* _gb = gB + (size_t)((c) & 31) * 128; \
        _Pragma("unroll") \
        for (int j = 0; j < 4; j++) CP_ASYNC16(_sa + so[j], _ga + j * jstrA); \
        _Pragma("unroll") \
        for (int j = 0; j < 4; j++) CP_ASYNC16(_sa + 16384 + so[j], _gb + j * jstrB); \
        CP_COMMIT(); \
    } while (0)

    float acc[4][4][4];
#pragma unroll
    for (int i = 0; i < 4; i++)
#pragma unroll
        for (int j = 0; j < 4; j++)
#pragma unroll
            for (int q = 0; q < 4; q++) acc[i][j][q] = 0.f;

    LOAD_STAGE(0, 0);
    LOAD_STAGE(1, 1);

    for (int c = 0; c < NC; c++) {
        if (c < NC - 1) CP_WAIT(1); else CP_WAIT(0);
        __syncthreads();
        if (c + 2 < NC) LOAD_STAGE(c + 2, (c + 2) % 3);

        const uint32_t sa = sb + (c % 3) * STAGE_BYTES;
#pragma unroll
        for (int ks = 0; ks < 4; ks++) {
            uint32_t a[4][4], b[2][4];
#pragma unroll
            for (int mt = 0; mt < 4; mt++) {
                uint32_t addr = sa + pA[mt] + (((uint32_t)(ks * 32) + hiA) ^ xA[mt]);
                LDSM4(a[mt][0], a[mt][1], a[mt][2], a[mt][3], addr);
            }
#pragma unroll
            for (int nt2 = 0; nt2 < 2; nt2++) {
                uint32_t addr = sa + pB[nt2] + (((uint32_t)(ks * 32) + hiB) ^ xB[nt2]);
                LDSM4(b[nt2][0], b[nt2][1], b[nt2][2], b[nt2][3], addr);
            }
#pragma unroll
            for (int mt = 0; mt < 4; mt++)
#pragma unroll
                for (int nt = 0; nt < 4; nt++) {
                    const uint32_t* bb = b[nt >> 1];
                    int p = (nt & 1) * 2;
                    MMA16816(acc[mt][nt], a[mt], bb[p], bb[p + 1]);
                }
        }
    }
#undef LOAD_STAGE

    const float* bias = (gid == 0) ? bfp : (gid == 1) ? bcp : (gid == 2) ? bgp : nullptr;
    __half* Out = (gid == 0) ? g_F : (gid == 1) ? g_C : (gid == 2) ? g_G : g_CG;

#pragma unroll
    for (int mt = 0; mt < 4; mt++) {
        int r0 = m0 + wm + mt * 16 + (lid >> 2);
        float i0 = (gid < 3) ? g_invs[r0]     : 1.0f;
        float i1 = (gid < 3) ? g_invs[r0 + 8] : 1.0f;
#pragma unroll
        for (int nt = 0; nt < 4; nt++) {
            int col = n0 + wn + nt * 8 + (lid & 3) * 2;
            float b0 = bias ? bias[col]     : 0.f;
            float b1 = bias ? bias[col + 1] : 0.f;
            float v00 = fmaf(acc[mt][nt][0], i0, b0);
            float v01 = fmaf(acc[mt][nt][1], i0, b1);
            float v10 = fmaf(acc[mt][nt][2], i1, b0);
            float v11 = fmaf(acc[mt][nt][3], i1, b1);
            float s00 = fast_sigmoid(v00), s01 = fast_sigmoid(v01);
            float s10 = fast_sigmoid(v10), s11 = fast_sigmoid(v11);
            float o00, o01, o10, o11;
            if (gid == 1) { o00 = v00 * s00; o01 = v01 * s01; o10 = v10 * s10; o11 = v11 * s11; }
            else          { o00 = s00;       o01 = s01;       o10 = s10;       o11 = s11; }
            *(__half2*)&Out[(size_t)r0 * HH + col]       = __floats2half2_rn(o00, o01);
            *(__half2*)&Out[(size_t)(r0 + 8) * HH + col] = __floats2half2_rn(o10, o11);
        }
    }
}

// ===== 2) GEMM launch 1: gid {3(CG), 0(F), 1(C)} via z=0..2 =====
__global__ void __launch_bounds__(256, 2) gemm_mma_kernel(
    const float* __restrict__ bfp, const float* __restrict__ bcp, const float* __restrict__ bgp)
{
    extern __shared__ __align__(1024) char smem[];
    const int gid = (blockIdx.z + 3) & 3;       // z=0 -> CG (2x work) launches first
    gemm_tile(gid, blockIdx.x * 128, blockIdx.y * 128, smem, bfp, bcp, bgp);
}

// scan_p1 body (chunk products/sums); reads F, C, CG only
__device__ __forceinline__ void scan_p1_body(int idx, const float* __restrict__ X)
{
    const int h2 = idx & 1023;
    const int ch = (idx >> 10) & 15;
    const int b = idx >> 14;
    size_t base = ((size_t)(b * SS + ch * CT)) * HH + h2 * 2;
    float Ax = 1.f, Ay = 1.f, Sx = 0.f, Sy = 0.f;
#pragma unroll 8
    for (int t = 0; t < CT; t++, base += HH) {
        float2 fv = __half22float2(*(const __half2*)&g_F[base]);
        float2 cv = __half22float2(*(const __half2*)&g_C[base]);
        float2 gv = __half22float2(*(const __half2*)&g_CG[base]);
        float2 xv = *(const float2*)&X[base];
        float ox = 1.f - gv.x, oy = 1.f - gv.y;
        float ax = ox * fv.x, ay = oy * fv.y;
        float bx = fmaf(gv.x, xv.x, ox * (1.f - fv.x) * cv.x);
        float by = fmaf(gv.y, xv.y, oy * (1.f - fv.y) * cv.y);
        Sx = fmaf(ax, Sx, bx); Sy = fmaf(ay, Sy, by);
        Ax *= ax; Ay *= ay;
    }
    int o = (b * CH + ch) * HH + h2 * 2;
    *(float2*)&g_chA[o] = make_float2(Ax, Ay);
    *(float2*)&g_chS[o] = make_float2(Sx, Sy);
}

// ===== 3) fused: gemm-G tiles (bid<512) + scan_p1 blocks (bid>=512) =====
__global__ void __launch_bounds__(256, 2) gemmG_scan_kernel(
    const float* __restrict__ x,
    const float* __restrict__ bfp, const float* __restrict__ bcp, const float* __restrict__ bgp)
{
    extern __shared__ __align__(1024) char smem[];
    if (blockIdx.x < 512) {
        int m0 = (blockIdx.x & 31) * 128;   // m fastest -> B L2-resident
        int n0 = (blockIdx.x >> 5) * 128;
        gemm_tile(2, m0, n0, smem, bfp, bcp, bgp);
    } else {
        scan_p1_body((blockIdx.x - 512) * 256 + threadIdx.x, x);
    }
}

// ===== 4) scan combine + replay =====
__global__ __launch_bounds__(256) void scan_p2()
{
    const int idx = blockIdx.x * 256 + threadIdx.x;   // 0 .. 8191
    const int h2 = idx & 1023;
    const int b = idx >> 10;
    float2 hv = make_float2(0.f, 0.f);
#pragma unroll
    for (int ch = 0; ch < CH; ch++) {
        int o = (b * CH + ch) * HH + h2 * 2;
        *(float2*)&g_hin[o] = hv;
        float2 a = *(const float2*)&g_chA[o];
        float2 s = *(const float2*)&g_chS[o];
        hv.x = fmaf(a.x, hv.x, s.x);
        hv.y = fmaf(a.y, hv.y, s.y);
    }
}

__global__ __launch_bounds__(256) void scan_p3(
    const float* __restrict__ X, float* __restrict__ out)
{
    const int idx = blockIdx.x * 256 + threadIdx.x;   // 0 .. 131071
    const int h2 = idx & 1023;
    const int ch = (idx >> 10) & 15;
    const int b = idx >> 14;
    float2 hh = *(const float2*)&g_hin[(b * CH + ch) * HH + h2 * 2];
    size_t base = ((size_t)(b * SS + ch * CT)) * HH + h2 * 2;
#pragma unroll 8
    for (int t = 0; t < CT; t++, base += HH) {
        float2 fv = __half22float2(*(const __half2*)&g_F[base]);
        float2 cv = __half22float2(*(const __half2*)&g_C[base]);
        float2 gv = __half22float2(*(const __half2*)&g_G[base]);
        float2 cg = __half22float2(*(const __half2*)&g_CG[base]);
        float2 xv = *(const float2*)&X[base];
        float hnx = fv.x * hh.x + (1.f - fv.x) * cv.x;
        float hny = fv.y * hh.y + (1.f - fv.y) * cv.y;
        *(float2*)&out[base] = make_float2(gv.x * hnx, gv.y * hny);
        hh.x = cg.x * xv.x + (1.f - cg.x) * hnx;
        hh.y = cg.y * xv.y + (1.f - cg.y) * hny;
    }
}

// ======================= launch =======================
extern "C" void kernel_launch(void* const* d_in, const int* in_sizes, int n_in,
                              void* d_out, int out_size)
{
    (void)in_sizes; (void)n_in; (void)out_size;
    const float* x         = (const float*)d_in[0];
    const float* rms_scale = (const float*)d_in[1];
    const float* W_f       = (const float*)d_in[2];
    const float* W_c       = (const float*)d_in[3];
    const float* W_g       = (const float*)d_in[4];
    const float* b_f       = (const float*)d_in[5];
    const float* b_c       = (const float*)d_in[6];
    const float* b_g       = (const float*)d_in[7];
    float* out = (float*)d_out;

    cudaFuncSetAttribute(gemm_mma_kernel, cudaFuncAttributeMaxDynamicSharedMemorySize, GEMM_SMEM);
    cudaFuncSetAttribute(gemmG_scan_kernel, cudaFuncAttributeMaxDynamicSharedMemorySize, GEMM_SMEM);

    // prep: 4096 quantsplit blocks + 16384 weight-prep blocks, co-scheduled
    prep_kernel<<<MM + 4 * 4096, 256>>>(x, rms_scale, W_f, W_c, W_g);

    // GEMM units CG(2x), F, C
    {
        dim3 grd(MM / 128, HH / 128, 3);
        gemm_mma_kernel<<<grd, 256, GEMM_SMEM>>>(b_f, b_c, b_g);
    }

    // GEMM unit G fused with scan_p1 (reads F/C/CG; G written independently)
    gemmG_scan_kernel<<<512 + 512, 256, GEMM_SMEM>>>(x, b_f, b_c, b_g);

    scan_p2<<<BB * HH / 2 / 256, 256>>>();
    scan_p3<<<BB * CH * HH / 2 / 256, 256>>>(x, out);
}

// round 17
// speedup vs baseline: 1.0212x; 1.0212x over previous
#include <cuda_runtime.h>
#include <cuda_bf16.h>
#include <cuda_fp16.h>
#include <math.h>
#include <stdint.h>

// Problem dims (fixed by the dataset)
#define BB 8
#define SS 512
#define EE 2048
#define HH 2048
#define MM (BB*SS)   // 4096 rows
#define CH 16        // scan chunks
#define CT 32        // steps per chunk

// ---------------- scratch (__device__ globals; no allocation allowed) ----------------
__device__ __nv_bfloat16 g_Aq [(size_t)MM * EE];        // integer q as bf16 (exact)
__device__ float         g_invs[MM];                    // 1/s per row
__device__ __nv_bfloat16 g_Acg[(size_t)MM * 2 * EE];    // [hi | lo] split of x
__device__ __nv_bfloat16 g_Bf  [(size_t)HH * EE];       // W_f^T  [N,K]
__device__ __nv_bfloat16 g_Bc  [(size_t)HH * EE];       // W_c^T
__device__ __nv_bfloat16 g_Bg  [(size_t)HH * EE];       // W_g^T
__device__ __nv_bfloat16 g_Bcgn[(size_t)HH * EE];       // W_g native [N,K] (CG gate)
__device__ __align__(16) __half g_F [(size_t)MM * HH];  // gate in (0,1) -> fp16
__device__ __align__(16) __half g_C [(size_t)MM * HH];  // silu values -> fp16 (|c|<=~40)
__device__ __align__(16) __half g_G [(size_t)MM * HH];  // gate -> fp16
__device__ __align__(16) __half g_CG[(size_t)MM * HH];  // gate -> fp16
__device__ float g_chA[BB * CH * HH];
__device__ float g_chS[BB * CH * HH];

// ---------------- helpers ----------------
__device__ __forceinline__ uint32_t smem_u32(const void* p) {
    uint32_t a;
    asm("{ .reg .u64 t; cvta.to.shared.u64 t, %1; cvt.u32.u64 %0, t; }" : "=r"(a) : "l"(p));
    return a;
}
#define CP_ASYNC16(smem, gmem) \
    asm volatile("cp.async.cg.shared.global [%0], [%1], 16;" :: "r"((uint32_t)(smem)), "l"(gmem) : "memory")
#define CP_COMMIT() asm volatile("cp.async.commit_group;" ::: "memory")
#define CP_WAIT(n)  asm volatile("cp.async.wait_group %0;" :: "n"(n) : "memory")

#define LDSM4(r0, r1, r2, r3, addr) \
    asm volatile("ldmatrix.sync.aligned.m8n8.x4.shared.b16 {%0,%1,%2,%3}, [%4];" \
        : "=r"(r0), "=r"(r1), "=r"(r2), "=r"(r3) : "r"(addr))

#define MMA16816(d, a, b0, b1) \
    asm volatile("mma.sync.aligned.m16n8k16.row.col.f32.bf16.bf16.f32 " \
        "{%0,%1,%2,%3}, {%4,%5,%6,%7}, {%8,%9}, {%0,%1,%2,%3};" \
        : "+f"((d)[0]), "+f"((d)[1]), "+f"((d)[2]), "+f"((d)[3]) \
        : "r"((a)[0]), "r"((a)[1]), "r"((a)[2]), "r"((a)[3]), "r"(b0), "r"(b1))

#define SWZ(o) ((o) ^ ((((uint32_t)(o)) >> 3) & 0x70))

// FMA-only sigmoid (no MUFU): exp2 poly + Newton reciprocal, rel err ~1e-6
__device__ __forceinline__ float fast_sigmoid(float v) {
    float t = v * 1.4426950408889634f;
    t = fminf(fmaxf(t, -126.0f), 126.0f);
    float fi = rintf(t);
    float f = t - fi;
    float p = 1.3333558146428443e-3f;
    p = fmaf(p, f, 9.6181291976126507e-3f);
    p = fmaf(p, f, 5.5504108664821580e-2f);
    p = fmaf(p, f, 2.4022650695910071e-1f);
    p = fmaf(p, f, 6.9314718055994531e-1f);
    p = fmaf(p, f, 1.0f);
    float e = p * __int_as_float(((int)fi + 127) << 23);
    float a = 1.0f + e;
    float r = __int_as_float(0x7EF311C3 - __float_as_int(a));
    r = r * fmaf(-a, r, 2.0f);
    r = r * fmaf(-a, r, 2.0f);
    r = r * fmaf(-a, r, 2.0f);
    return e * r;
}

__device__ __forceinline__ void store8bf16(__nv_bfloat16* p, const float* f) {
    __nv_bfloat162 p0 = __floats2bfloat162_rn(f[0], f[1]);
    __nv_bfloat162 p1 = __floats2bfloat162_rn(f[2], f[3]);
    __nv_bfloat162 p2 = __floats2bfloat162_rn(f[4], f[5]);
    __nv_bfloat162 p3 = __floats2bfloat162_rn(f[6], f[7]);
    uint4 u;
    u.x = *(uint32_t*)&p0; u.y = *(uint32_t*)&p1;
    u.z = *(uint32_t*)&p2; u.w = *(uint32_t*)&p3;
    *(uint4*)p = u;
}

// ===== 1) fused: rms_norm + act_quant (q as bf16) + hi/lo split of raw x =====
__global__ __launch_bounds__(256) void quantsplit_kernel(
    const float* __restrict__ x, const float* __restrict__ rms_scale)
{
    const int row = blockIdx.x;
    const float* xr = x + (size_t)row * EE;
    const int tid = threadIdx.x;

    __shared__ float red_a[8], red_b[8];
    __shared__ float bcast[2];

    float v[8];
    float ss = 0.f;
#pragma unroll
    for (int i = 0; i < 8; i += 4) {
        float4 t4 = *(const float4*)(xr + tid * 8 + i);
        v[i] = t4.x; v[i+1] = t4.y; v[i+2] = t4.z; v[i+3] = t4.w;
    }
#pragma unroll
    for (int i = 0; i < 8; i++) ss += v[i] * v[i];
#pragma unroll
    for (int o = 16; o; o >>= 1) ss += __shfl_xor_sync(0xffffffffu, ss, o);
    if ((tid & 31) == 0) red_a[tid >> 5] = ss;
    __syncthreads();
    if (tid == 0) {
        float t = 0.f;
#pragma unroll
        for (int w = 0; w < 8; w++) t += red_a[w];
        bcast[0] = 1.0f / sqrtf(t / (float)EE + 1e-5f);
    }
    __syncthreads();
    const float rms = bcast[0];

    // hi/lo split of raw x (independent of rms path)
    {
        float hi[8], lo[8];
#pragma unroll
        for (int i = 0; i < 8; i++) {
            __nv_bfloat16 h = __float2bfloat16(v[i]);
            hi[i] = __bfloat162float(h);
            lo[i] = v[i] - hi[i];
        }
        size_t off = (size_t)row * (2 * EE) + tid * 8;
        store8bf16(g_Acg + off, hi);
        store8bf16(g_Acg + off + EE, lo);
    }

    float sv[8];
    float msc = 0.f;
#pragma unroll
    for (int i = 0; i < 8; i++) {
        sv[i] = v[i] * rms * rms_scale[tid * 8 + i];
        msc = fmaxf(msc, fabsf(sv[i]));
    }
#pragma unroll
    for (int o = 16; o; o >>= 1) msc = fmaxf(msc, __shfl_xor_sync(0xffffffffu, msc, o));
    if ((tid & 31) == 0) red_b[tid >> 5] = msc;
    __syncthreads();
    if (tid == 0) {
        float m = 0.f;
#pragma unroll
        for (int w = 0; w < 8; w++) m = fmaxf(m, red_b[w]);
        float s = 127.0f / (m + 1e-5f);
        s = fminf(fmaxf(s, 0.001f), 1000.0f);
        bcast[1] = s;
        g_invs[row] = 1.0f / s;
    }
    __syncthreads();
    const float s = bcast[1];
    {
        float q[8];
#pragma unroll
        for (int i = 0; i < 8; i++) {
            float qq = rintf(s * sv[i]);                 // ties-to-even == jnp.round
            q[i] = fminf(fmaxf(qq, -128.0f), 127.0f);
        }
        store8bf16(g_Aq + (size_t)row * EE + tid * 8, q);   // exact integers in bf16
    }
}

// ===== 2) weight prep: z<3 transpose+convert; z=3 direct convert of W_g (native [N,K]) =====
__global__ __launch_bounds__(256) void wtrans_kernel(
    const float* __restrict__ Wf, const float* __restrict__ Wc, const float* __restrict__ Wg)
{
    if (blockIdx.z == 3) {
        int xI = blockIdx.x * 32 + threadIdx.x;
        int yI = blockIdx.y * 32 + threadIdx.y;
#pragma unroll
        for (int j = 0; j < 32; j += 8) {
            size_t idx = (size_t)(yI + j) * EE + xI;
            g_Bcgn[idx] = __float2bfloat16(Wg[idx]);
        }
        return;
    }
    const float* in = (blockIdx.z == 0) ? Wf : (blockIdx.z == 1) ? Wc : Wg;
    __nv_bfloat16* out = (blockIdx.z == 0) ? g_Bf : (blockIdx.z == 1) ? g_Bc : g_Bg;
    __shared__ float tile[32][33];
    int xI = blockIdx.x * 32 + threadIdx.x;  // H index (contig in input)
    int yI = blockIdx.y * 32 + threadIdx.y;  // E index
#pragma unroll
    for (int j = 0; j < 32; j += 8)
        tile[threadIdx.y + j][threadIdx.x] = in[(size_t)(yI + j) * HH + xI];
    __syncthreads();
    xI = blockIdx.y * 32 + threadIdx.x;      // E index (contig in output)
    yI = blockIdx.x * 32 + threadIdx.y;      // H index
#pragma unroll
    for (int j = 0; j < 32; j += 8)
        out[(size_t)(yI + j) * EE + xI] = __float2bfloat16(tile[threadIdx.x][threadIdx.y + j]);
}

// ===== 3) bf16 mma.sync GEMM (round-7 mainloop), fused epilogue =====
// gid: 0 F=sigmoid(q@Bf*inv+bf) 1 C=silu 2 G=sigmoid 3 CG=sigmoid([hi|lo]x @ Wg, B wraps K)
#define STAGES 3
#define STAGE_BYTES 32768                       // 16KB A + 16KB B (128 rows x 128B)
#define GEMM_SMEM (STAGES * STAGE_BYTES)        // 96 KB -> 2 CTAs/SM

__global__ void __launch_bounds__(256, 2) gemm_mma_kernel(
    const float* __restrict__ bfp, const float* __restrict__ bcp, const float* __restrict__ bgp)
{
    extern __shared__ __align__(1024) char smem[];
    const uint32_t sb = smem_u32(smem);
    const int tid = threadIdx.x, wid = tid >> 5, lid = tid & 31;
    const int gid = (blockIdx.z + 3) & 3;       // z=0 -> CG (2x work) launches first
    const int m0 = blockIdx.x * 128, n0 = blockIdx.y * 128;
    const int K = (gid == 3) ? 2 * EE : EE;
    const int NC = K / 64;
    const size_t Kz = (size_t)K;

    const __nv_bfloat16* A = (gid == 3) ? g_Acg : g_Aq;
    const __nv_bfloat16* B = (gid == 0) ? g_Bf : (gid == 1) ? g_Bc : (gid == 2) ? g_Bg : g_Bcgn;

    const int wm = (wid >> 2) * 64;   // warp m offset (0/64)
    const int wn = (wid & 3) * 32;    // warp n offset (0/32/64/96)

    // Precomputed LDSM addressing: SWZ(row*128 + k) == row*128 + (k ^ ((row&7)*16)) for k<128
    uint32_t pA[4], xA[4];
#pragma unroll
    for (int mt = 0; mt < 4; mt++) {
        int row = wm + mt * 16 + (lid & 15);
        pA[mt] = (uint32_t)row * 128;
        xA[mt] = (uint32_t)(row & 7) * 16;
    }
    const uint32_t hiA = (lid >> 4) * 16;
    uint32_t pB[2], xB[2];
#pragma unroll
    for (int nt2 = 0; nt2 < 2; nt2++) {
        int row = wn + nt2 * 16 + (lid & 7) + ((lid >> 4) & 1) * 8;
        pB[nt2] = (uint32_t)row * 128 + 16384;
        xB[nt2] = (uint32_t)(row & 7) * 16;
    }
    const uint32_t hiB = ((lid >> 3) & 1) * 16;

    // Strength-reduced load addressing (loop-invariant parts hoisted)
    // A row stride = Kz (2*EE for CG); B row stride = EE always (chunk index wraps with c&31)
    const int row0 = tid >> 3, c16 = tid & 7;
    const char* gA = (const char*)A + ((size_t)(m0 + row0) * Kz) * 2 + c16 * 16;
    const char* gB = (const char*)B + ((size_t)(n0 + row0) * EE) * 2 + c16 * 16;
    const size_t jstrA = (size_t)32 * Kz * 2;   // +32 rows (A)
    const size_t jstrB = (size_t)32 * EE * 2;   // +32 rows (B)
    uint32_t so[4];
#pragma unroll
    for (int j = 0; j < 4; j++) so[j] = SWZ((uint32_t)(row0 + 32 * j) * 128 + c16 * 16);

#define LOAD_STAGE(c, s) do { \
        uint32_t _sa = sb + (s) * STAGE_BYTES; \
        const char* _ga = gA + (size_t)(c) * 128; \
        const char* _gb = gB + (size_t)((c) & 31) * 128; \
        _Pragma("unroll") \
        for (int j = 0; j < 4; j++) CP_ASYNC16(_sa + so[j], _ga + j * jstrA); \
        _Pragma("unroll") \
        for (int j = 0; j < 4; j++) CP_ASYNC16(_sa + 16384 + so[j], _gb + j * jstrB); \
        CP_COMMIT(); \
    } while (0)

    float acc[4][4][4];
#pragma unroll
    for (int i = 0; i < 4; i++)
#pragma unroll
        for (int j = 0; j < 4; j++)
#pragma unroll
            for (int q = 0; q < 4; q++) acc[i][j][q] = 0.f;

    LOAD_STAGE(0, 0);
    LOAD_STAGE(1, 1);

    for (int c = 0; c < NC; c++) {
        if (c < NC - 1) CP_WAIT(1); else CP_WAIT(0);
        __syncthreads();                           // single barrier per chunk
        if (c + 2 < NC) LOAD_STAGE(c + 2, (c + 2) % 3);  // overlaps with MMA below

        const uint32_t sa = sb + (c % 3) * STAGE_BYTES;
#pragma unroll
        for (int ks = 0; ks < 4; ks++) {
            uint32_t a[4][4], b[2][4];
#pragma unroll
            for (int mt = 0; mt < 4; mt++) {
                uint32_t addr = sa + pA[mt] + (((uint32_t)(ks * 32) + hiA) ^ xA[mt]);
                LDSM4(a[mt][0], a[mt][1], a[mt][2], a[mt][3], addr);
            }
#pragma unroll
            for (int nt2 = 0; nt2 < 2; nt2++) {
                uint32_t addr = sa + pB[nt2] + (((uint32_t)(ks * 32) + hiB) ^ xB[nt2]);
                LDSM4(b[nt2][0], b[nt2][1], b[nt2][2], b[nt2][3], addr);
            }
#pragma unroll
            for (int mt = 0; mt < 4; mt++)
#pragma unroll
                for (int nt = 0; nt < 4; nt++) {
                    const uint32_t* bb = b[nt >> 1];
                    int p = (nt & 1) * 2;
                    MMA16816(acc[mt][nt], a[mt], bb[p], bb[p + 1]);
                }
        }
    }

    // -------- epilogue (no MUFU); all outputs fp16 --------
    const float* bias = (gid == 0) ? bfp : (gid == 1) ? bcp : (gid == 2) ? bgp : nullptr;
    __half* Out = (gid == 0) ? g_F : (gid == 1) ? g_C : (gid == 2) ? g_G : g_CG;

#pragma unroll
    for (int mt = 0; mt < 4; mt++) {
        int r0 = m0 + wm + mt * 16 + (lid >> 2);
        float i0 = (gid < 3) ? g_invs[r0]     : 1.0f;
        float i1 = (gid < 3) ? g_invs[r0 + 8] : 1.0f;
#pragma unroll
        for (int nt = 0; nt < 4; nt++) {
            int col = n0 + wn + nt * 8 + (lid & 3) * 2;
            float b0 = bias ? bias[col]     : 0.f;
            float b1 = bias ? bias[col + 1] : 0.f;
            float v00 = fmaf(acc[mt][nt][0], i0, b0);
            float v01 = fmaf(acc[mt][nt][1], i0, b1);
            float v10 = fmaf(acc[mt][nt][2], i1, b0);
            float v11 = fmaf(acc[mt][nt][3], i1, b1);
            float s00 = fast_sigmoid(v00), s01 = fast_sigmoid(v01);
            float s10 = fast_sigmoid(v10), s11 = fast_sigmoid(v11);
            float o00, o01, o10, o11;
            if (gid == 1) { o00 = v00 * s00; o01 = v01 * s01; o10 = v10 * s10; o11 = v11 * s11; }
            else          { o00 = s00;       o01 = s01;       o10 = s10;       o11 = s11; }
            *(__half2*)&Out[(size_t)r0 * HH + col]       = __floats2half2_rn(o00, o01);
            *(__half2*)&Out[(size_t)(r0 + 8) * HH + col] = __floats2half2_rn(o10, o11);
        }
    }
}

// ===== 4) chunked parallel scan: p1 per-chunk (A,S); p3 folds prefix inline + replay =====
__global__ __launch_bounds__(256) void scan_p1(const float* __restrict__ X)
{
    const int idx = blockIdx.x * 256 + threadIdx.x;   // 0 .. 131071
    const int h2 = idx & 1023;                        // pair index
    const int ch = (idx >> 10) & 15;
    const int b = idx >> 14;
    size_t base = ((size_t)(b * SS + ch * CT)) * HH + h2 * 2;
    float Ax = 1.f, Ay = 1.f, Sx = 0.f, Sy = 0.f;
#pragma unroll 8
    for (int t = 0; t < CT; t++, base += HH) {
        float2 fv = __half22float2(*(const __half2*)&g_F[base]);
        float2 cv = __half22float2(*(const __half2*)&g_C[base]);
        float2 gv = __half22float2(*(const __half2*)&g_CG[base]);
        float2 xv = *(const float2*)&X[base];
        float ox = 1.f - gv.x, oy = 1.f - gv.y;
        float ax = ox * fv.x, ay = oy * fv.y;
        float bx = fmaf(gv.x, xv.x, ox * (1.f - fv.x) * cv.x);
        float by = fmaf(gv.y, xv.y, oy * (1.f - fv.y) * cv.y);
        Sx = fmaf(ax, Sx, bx); Sy = fmaf(ay, Sy, by);
        Ax *= ax; Ay *= ay;
    }
    int o = (b * CH + ch) * HH + h2 * 2;
    *(float2*)&g_chA[o] = make_float2(Ax, Ay);
    *(float2*)&g_chS[o] = make_float2(Sx, Sy);
}

__global__ __launch_bounds__(256) void scan_p3(
    const float* __restrict__ X, float* __restrict__ out)
{
    const int idx = blockIdx.x * 256 + threadIdx.x;   // 0 .. 131071
    const int h2 = idx & 1023;
    const int ch = (idx >> 10) & 15;
    const int b = idx >> 14;

    // fold chunk prefixes 0..ch-1 inline (replaces scan_p2 kernel + g_hin traffic)
    float2 hh = make_float2(0.f, 0.f);
    {
        int o = b * CH * HH + h2 * 2;
        for (int c2 = 0; c2 < ch; c2++, o += HH) {
            float2 a = *(const float2*)&g_chA[o];
            float2 s = *(const float2*)&g_chS[o];
            hh.x = fmaf(a.x, hh.x, s.x);
            hh.y = fmaf(a.y, hh.y, s.y);
        }
    }

    size_t base = ((size_t)(b * SS + ch * CT)) * HH + h2 * 2;
#pragma unroll 8
    for (int t = 0; t < CT; t++, base += HH) {
        float2 fv = __half22float2(*(const __half2*)&g_F[base]);
        float2 cv = __half22float2(*(const __half2*)&g_C[base]);
        float2 gv = __half22float2(*(const __half2*)&g_G[base]);
        float2 cg = __half22float2(*(const __half2*)&g_CG[base]);
        float2 xv = *(const float2*)&X[base];
        float hnx = fv.x * hh.x + (1.f - fv.x) * cv.x;
        float hny = fv.y * hh.y + (1.f - fv.y) * cv.y;
        *(float2*)&out[base] = make_float2(gv.x * hnx, gv.y * hny);
        hh.x = cg.x * xv.x + (1.f - cg.x) * hnx;
        hh.y = cg.y * xv.y + (1.f - cg.y) * hny;
    }
}

// ======================= launch =======================
extern "C" void kernel_launch(void* const* d_in, const int* in_sizes, int n_in,
                              void* d_out, int out_size)
{
    (void)in_sizes; (void)n_in; (void)out_size;
    const float* x         = (const float*)d_in[0];
    const float* rms_scale = (const float*)d_in[1];
    const float* W_f       = (const float*)d_in[2];
    const float* W_c       = (const float*)d_in[3];
    const float* W_g       = (const float*)d_in[4];
    const float* b_f       = (const float*)d_in[5];
    const float* b_c       = (const float*)d_in[6];
    const float* b_g       = (const float*)d_in[7];
    float* out = (float*)d_out;

    cudaFuncSetAttribute(gemm_mma_kernel, cudaFuncAttributeMaxDynamicSharedMemorySize, GEMM_SMEM);

    quantsplit_kernel<<<MM, 256>>>(x, rms_scale);
    {
        dim3 blk(32, 8), grd(HH / 32, EE / 32, 4);   // z=3 = native W_g convert (CG gate B)
        wtrans_kernel<<<grd, blk>>>(W_f, W_c, W_g);
    }
    {
        dim3 grd(MM / 128, HH / 128, 4);   // x fastest -> B L2-resident; z=0 is CG (2x work)
        gemm_mma_kernel<<<grd, 256, GEMM_SMEM>>>(b_f, b_c, b_g);
    }
    scan_p1<<<BB * CH * HH / 2 / 256, 256>>>(x);
    scan_p3<<<BB * CH * HH / 2 / 256, 256>>>(x, out);
}